// round 1
// baseline (speedup 1.0000x reference)
#include <cuda_runtime.h>
#include <cstdint>

#define Bb 32
#define Ss 2048
#define Hh 512
#define Ee 512
#define NROWS (Bb*Ss)

#define TM 64
#define KB 32
#define NC 128
#define ASTRIDE 516   // 512 + 4 pad to break bank conflicts on a-column reads

// Scratch (allocation-free rule: __device__ globals)
__device__ float g_dec_proj[Bb*Hh];
__device__ float g_wc_sum[Hh];
__device__ float g_att[Bb*Ss];

__device__ __forceinline__ float fast_tanh(float x) {
    // tanh(x) = 1 - 2/(e^{2x}+1); e=inf -> 1, e=0 -> -1. MUFU-based, ~2 ulp-ish, fine vs 1e-3.
    float e = __expf(2.0f * x);
    return 1.0f - 2.0f * __fdividef(1.0f, e + 1.0f);
}

// ---------------------------------------------------------------------------
// Kernel 0: dec_proj[b][h] = sum_e dec[b][e] * W_s[e][h];  wc_sum[h] = sum_k W_cov[k][h]
// ---------------------------------------------------------------------------
__global__ void prep_kernel(const float* __restrict__ dec_input,
                            const float* __restrict__ W) {
    int blk = blockIdx.x;
    int h = threadIdx.x;           // blockDim = 512
    if (blk < Bb) {
        __shared__ float s_dec[Ee];
        s_dec[h] = dec_input[blk*Ee + h];
        __syncthreads();
        const float* Ws = W + (size_t)Hh * Hh;   // W_s = rows [H, H+E)
        float acc = 0.f;
        #pragma unroll 8
        for (int e = 0; e < Ee; e++)
            acc += s_dec[e] * Ws[(size_t)e*Hh + h];
        g_dec_proj[blk*Hh + h] = acc;
    } else {
        const float* Wc = W + (size_t)(Hh + Ee) * Hh; // W_cov = rows [H+E, ...)
        float acc = 0.f;
        #pragma unroll 8
        for (int k = 0; k < Hh; k++)
            acc += Wc[(size_t)k*Hh + h];
        g_wc_sum[h] = acc;
    }
}

// ---------------------------------------------------------------------------
// Kernel 1: fused GEMM (enc @ W_enc) + broadcast adds + tanh + v_w reduction
// grid = NROWS/TM blocks, 256 threads; each thread: 4 rows x 8 cols micro-tile
// ---------------------------------------------------------------------------
__global__ __launch_bounds__(256, 1) void fused_gemm_kernel(
    const float* __restrict__ enc,
    const float* __restrict__ cov,
    const float* __restrict__ W,        // W_enc = rows [0,H)
    const float* __restrict__ bias,
    const float* __restrict__ v_w)
{
    extern __shared__ float smem[];
    float* As = smem;                   // TM x ASTRIDE
    float* Bs = smem + TM * ASTRIDE;    // KB x NC
    __shared__ float s_cov[TM];

    const int tid = threadIdx.x;
    const int tx = tid & 15;
    const int ty = tid >> 4;
    const int row0 = blockIdx.x * TM;
    const int b = row0 >> 11;           // S = 2048

    // Load full A tile (64 x 512) via float4, padded smem rows
    {
        const float4* encv = (const float4*)(enc + (size_t)row0 * Hh);
        #pragma unroll
        for (int i = 0; i < (TM*Hh/4)/256; i++) {     // 32 iters
            int idx = tid + i*256;
            int r  = idx >> 7;       // 128 float4 per row
            int c4 = idx & 127;
            float4 v = encv[r*128 + c4];
            float* dst = As + r*ASTRIDE + c4*4;
            dst[0]=v.x; dst[1]=v.y; dst[2]=v.z; dst[3]=v.w;
        }
        if (tid < TM) s_cov[tid] = cov[row0 + tid];
    }
    __syncthreads();

    float partial[4] = {0.f, 0.f, 0.f, 0.f};

    #pragma unroll 1
    for (int n0 = 0; n0 < Hh; n0 += NC) {
        float acc[4][8];
        #pragma unroll
        for (int r = 0; r < 4; r++)
            #pragma unroll
            for (int c = 0; c < 8; c++) acc[r][c] = 0.f;

        #pragma unroll 1
        for (int k0 = 0; k0 < Hh; k0 += KB) {
            __syncthreads();   // protect Bs from previous iteration readers
            // Load W tile KB x NC
            #pragma unroll
            for (int i = 0; i < (KB*NC/4)/256; i++) {  // 4 iters
                int idx = tid + i*256;
                int kr = idx >> 5;     // 32 float4 per row
                int c4 = idx & 31;
                float4 v = *(const float4*)(W + (size_t)(k0+kr)*Hh + n0 + c4*4);
                *(float4*)(Bs + kr*NC + c4*4) = v;
            }
            __syncthreads();

            #pragma unroll 8
            for (int kk = 0; kk < KB; kk++) {
                float a[4];
                #pragma unroll
                for (int r = 0; r < 4; r++)
                    a[r] = As[(ty*4 + r)*ASTRIDE + k0 + kk];
                float bf[8];
                #pragma unroll
                for (int j = 0; j < 2; j++) {
                    float4 v = *(const float4*)(Bs + kk*NC + tx*8 + j*4);
                    bf[j*4+0]=v.x; bf[j*4+1]=v.y; bf[j*4+2]=v.z; bf[j*4+3]=v.w;
                }
                #pragma unroll
                for (int r = 0; r < 4; r++)
                    #pragma unroll
                    for (int c = 0; c < 8; c++)
                        acc[r][c] = fmaf(a[r], bf[c], acc[r][c]);
            }
        }

        // Epilogue for this N-chunk: z = acc + dec_proj + cov*wc_sum + bias; partial += v_w*tanh(z)
        #pragma unroll
        for (int c = 0; c < 8; c++) {
            int n = n0 + tx*8 + c;
            float d   = g_dec_proj[b*Hh + n] + bias[n];
            float wcs = g_wc_sum[n];
            float vw  = v_w[n];
            #pragma unroll
            for (int r = 0; r < 4; r++) {
                float z = acc[r][c] + d + s_cov[ty*4 + r] * wcs;
                partial[r] += vw * fast_tanh(z);
            }
        }
    }

    // Reduce partial over the 16 tx lanes (xor <= 8 stays within half-warp)
    #pragma unroll
    for (int r = 0; r < 4; r++) {
        float v = partial[r];
        #pragma unroll
        for (int m = 8; m >= 1; m >>= 1)
            v += __shfl_xor_sync(0xffffffffu, v, m);
        if (tx == 0)
            g_att[row0 + ty*4 + r] = v;
    }
}

// ---------------------------------------------------------------------------
// Kernel 2: masked softmax over S per batch + new_coverage
// out[0 .. B*S)        = attention_weights
// out[B*S .. 2*B*S)    = coverage + attention_weights
// ---------------------------------------------------------------------------
__global__ void softmax_kernel(const int* __restrict__ lens,
                               const float* __restrict__ cov,
                               float* __restrict__ out) {
    __shared__ float s[Ss];
    __shared__ float red[9];
    const int b = blockIdx.x;
    const int tid = threadIdx.x;    // 256
    const int len = lens[b];
    const float NEG_INF = __int_as_float(0xff800000);

    float mx = NEG_INF;
    for (int i = tid; i < Ss; i += 256) {
        float v = (i < len) ? g_att[b*Ss + i] : NEG_INF;
        s[i] = v;
        mx = fmaxf(mx, v);
    }
    #pragma unroll
    for (int m = 16; m >= 1; m >>= 1)
        mx = fmaxf(mx, __shfl_xor_sync(0xffffffffu, mx, m));
    if ((tid & 31) == 0) red[tid >> 5] = mx;
    __syncthreads();
    if (tid == 0) {
        float m = red[0];
        #pragma unroll
        for (int i = 1; i < 8; i++) m = fmaxf(m, red[i]);
        red[8] = m;
    }
    __syncthreads();
    mx = red[8];

    float sum = 0.f;
    for (int i = tid; i < Ss; i += 256) {
        float e = __expf(s[i] - mx);   // exp(-inf) = 0 for masked slots
        s[i] = e;
        sum += e;
    }
    #pragma unroll
    for (int m = 16; m >= 1; m >>= 1)
        sum += __shfl_xor_sync(0xffffffffu, sum, m);
    __syncthreads();
    if ((tid & 31) == 0) red[tid >> 5] = sum;
    __syncthreads();
    if (tid == 0) {
        float t = 0.f;
        #pragma unroll
        for (int i = 0; i < 8; i++) t += red[i];
        red[8] = t;
    }
    __syncthreads();
    const float inv = __fdividef(1.0f, red[8]);

    for (int i = tid; i < Ss; i += 256) {
        float w = s[i] * inv;
        out[b*Ss + i] = w;
        out[Bb*Ss + b*Ss + i] = cov[b*Ss + i] + w;
    }
}

// ---------------------------------------------------------------------------
extern "C" void kernel_launch(void* const* d_in, const int* in_sizes, int n_in,
                              void* d_out, int out_size) {
    const float* dec_input = (const float*)d_in[0];
    const float* enc       = (const float*)d_in[1];
    const int*   lens      = (const int*)  d_in[2];
    const float* cov       = (const float*)d_in[3];
    const float* W         = (const float*)d_in[4];
    const float* bias      = (const float*)d_in[5];
    const float* v_w       = (const float*)d_in[6];
    // d_in[7] = v_b: uniform logit shift, softmax-invariant -> unused.
    float* out = (float*)d_out;

    prep_kernel<<<Bb + 1, 512>>>(dec_input, W);

    size_t smem = (size_t)(TM*ASTRIDE + KB*NC) * sizeof(float);   // ~148 KB
    cudaFuncSetAttribute(fused_gemm_kernel,
                         cudaFuncAttributeMaxDynamicSharedMemorySize, (int)smem);
    fused_gemm_kernel<<<NROWS/TM, 256, smem>>>(enc, cov, W, bias, v_w);

    softmax_kernel<<<Bb, 256>>>(lens, cov, out);
}

// round 3
// speedup vs baseline: 4.1573x; 4.1573x over previous
#include <cuda_runtime.h>
#include <cstdint>

#define Bb 32
#define Ss 2048
#define Hh 512
#define Ee 512
#define NROWS (Bb*Ss)

#define MT 128              // M rows per CTA
#define NT 128              // N cols per CTA (N-block)
#define KC 32               // K floats per pipeline chunk
#define NKCH (Hh/KC)        // 16
#define AST 36              // padded smem row stride (floats): 144B, 16B-aligned
#define TILE_F (128*AST)    // floats per A or B tile
#define BUF_BYTES (2*TILE_F*4)        // A+B one stage: 36864
#define SMEM_DYN  (2*BUF_BYTES)       // double buffered: 73728

// ---- device scratch ----
__device__ float g_Wt[Hh*Hh];           // W_enc^T [n][k], tf32-rounded
__device__ float g_dvec[Bb*Hh];         // dec_proj + bias
__device__ float g_wc_sum[Hh];
__device__ float g_att_part[4*NROWS];   // per-N-block partial logits

__device__ __forceinline__ uint32_t smem_u32(const void* p) {
    uint32_t a;
    asm("{ .reg .u64 t; cvta.to.shared.u64 t, %1; cvt.u32.u64 %0, t; }" : "=r"(a) : "l"(p));
    return a;
}
#define CP16(dst, src) asm volatile("cp.async.cg.shared.global [%0], [%1], 16;" :: "r"(dst), "l"(src))
#define CP_COMMIT()    asm volatile("cp.async.commit_group;" ::: "memory")
#define CP_WAIT1()     asm volatile("cp.async.wait_group 1;" ::: "memory")
#define CP_WAIT0()     asm volatile("cp.async.wait_group 0;" ::: "memory")

__device__ __forceinline__ void mma_tf32(float* c, uint32_t a0, uint32_t a1,
                                         uint32_t a2, uint32_t a3,
                                         uint32_t b0, uint32_t b1) {
    asm volatile(
        "mma.sync.aligned.m16n8k8.row.col.f32.tf32.tf32.f32 "
        "{%0,%1,%2,%3}, {%4,%5,%6,%7}, {%8,%9}, {%0,%1,%2,%3};"
        : "+f"(c[0]), "+f"(c[1]), "+f"(c[2]), "+f"(c[3])
        : "r"(a0), "r"(a1), "r"(a2), "r"(a3), "r"(b0), "r"(b1));
}

// ---------------------------------------------------------------------------
// prep: W_enc^T (tf32-rounded), dvec = dec@W_s + bias, wc_sum = colsum(W_cov)
// ---------------------------------------------------------------------------
__global__ void prep_kernel(const float* __restrict__ dec_input,
                            const float* __restrict__ W,
                            const float* __restrict__ bias) {
    const int blk = blockIdx.x, tid = threadIdx.x;
    if (blk < 256) {                       // transpose 32x32 tiles
        __shared__ float t[32][33];
        const int bc = blk & 15, br = blk >> 4;
        const int lx = tid & 31, ly = tid >> 5;
        #pragma unroll
        for (int i = 0; i < 4; i++)
            t[ly + 8*i][lx] = W[(size_t)(br*32 + ly + 8*i)*Hh + bc*32 + lx];
        __syncthreads();
        #pragma unroll
        for (int i = 0; i < 4; i++) {
            float v = t[lx][ly + 8*i];
            uint32_t r;
            asm("cvt.rna.tf32.f32 %0, %1;" : "=r"(r) : "f"(v));
            g_Wt[(size_t)(bc*32 + ly + 8*i)*Hh + br*32 + lx] = __uint_as_float(r);
        }
    } else if (blk < 288) {                // dec_proj + bias
        const int b = blk - 256;
        __shared__ float sdec[Ee];
        for (int i = tid; i < Ee; i += 256) sdec[i] = dec_input[b*Ee + i];
        __syncthreads();
        const float* Ws = W + (size_t)Hh * Hh;
        for (int h = tid; h < Hh; h += 256) {
            float acc = bias[h];
            #pragma unroll 8
            for (int e = 0; e < Ee; e++)
                acc = fmaf(sdec[e], Ws[(size_t)e*Hh + h], acc);
            g_dvec[b*Hh + h] = acc;
        }
    } else {                               // wc_sum
        const float* Wc = W + (size_t)(Hh + Ee) * Hh;
        for (int h = tid; h < Hh; h += 256) {
            float a = 0.f;
            #pragma unroll 8
            for (int k = 0; k < Hh; k++) a += Wc[(size_t)k*Hh + h];
            g_wc_sum[h] = a;
        }
    }
}

// ---------------------------------------------------------------------------
// GEMM: enc(128xK) @ W_enc(KxNT) via mma.sync tf32 + fused epilogue
// grid = 2048 (blockIdx: low 2 bits = N-block, rest = M-tile), 256 threads
// ---------------------------------------------------------------------------
__global__ __launch_bounds__(256, 2) void gemm_kernel(
    const float* __restrict__ enc,
    const float* __restrict__ cov,
    const float* __restrict__ v_w)
{
    extern __shared__ char sdyn[];
    __shared__ float s_dvec[NT], s_wc[NT], s_vw[NT], s_cov[MT];

    const int tid  = threadIdx.x;
    const int wid  = tid >> 5, lane = tid & 31;
    const int gid  = lane >> 2, qid = lane & 3;
    const int wm   = wid >> 1, wn = wid & 1;       // 4x2 warp grid
    const int nb   = blockIdx.x & 3;
    const int row0 = (blockIdx.x >> 2) * MT;
    const int n0g  = nb * NT;
    const int b    = row0 >> 11;

    // epilogue constants
    for (int i = tid; i < NT; i += 256) {
        s_dvec[i] = g_dvec[b*Hh + n0g + i];
        s_wc[i]   = g_wc_sum[n0g + i];
        s_vw[i]   = v_w[n0g + i];
    }
    if (tid < MT) s_cov[tid] = cov[row0 + tid];

    const uint32_t sb = smem_u32(sdyn);
    const int r_ld = tid >> 3, c4_ld = tid & 7;    // 16B-chunk loader coords

    // issue chunk kc into buffer buf
    auto issue = [&](int kc, int buf) {
        const uint32_t abase = sb + buf*BUF_BYTES;
        const uint32_t bbase = abase + TILE_F*4;
        const float* srcA = enc + (size_t)row0*Hh + kc*KC;
        const float* srcB = g_Wt + (size_t)n0g*Hh + kc*KC;
        #pragma unroll
        for (int j = 0; j < 4; j++) {
            int row = r_ld + j*32;
            CP16(abase + row*(AST*4) + c4_ld*16, srcA + (size_t)row*Hh + c4_ld*4);
            CP16(bbase + row*(AST*4) + c4_ld*16, srcB + (size_t)row*Hh + c4_ld*4);
        }
    };

    float acc[2][8][4];
    #pragma unroll
    for (int mi = 0; mi < 2; mi++)
        #pragma unroll
        for (int j = 0; j < 8; j++)
            #pragma unroll
            for (int c = 0; c < 4; c++) acc[mi][j][c] = 0.f;

    issue(0, 0);
    CP_COMMIT();

    #pragma unroll 1
    for (int kc = 0; kc < NKCH; kc++) {
        if (kc < NKCH - 1) { issue(kc + 1, (kc + 1) & 1); CP_COMMIT(); }
        if (kc < NKCH - 1) CP_WAIT1(); else CP_WAIT0();
        __syncthreads();

        const float* As = (const float*)(sdyn + (kc & 1)*BUF_BYTES);
        const float* Bs = As + TILE_F;
        const int ra = wm*32 + gid;
        const int nbase = wn*64 + gid;

        #pragma unroll
        for (int ks = 0; ks < 4; ks++) {
            const int k = ks*8 + qid;
            uint32_t a[2][4];
            #pragma unroll
            for (int mi = 0; mi < 2; mi++) {
                const float* ap = As + (ra + mi*16)*AST + k;
                a[mi][0] = __float_as_uint(ap[0]);
                a[mi][1] = __float_as_uint(ap[8*AST]);
                a[mi][2] = __float_as_uint(ap[4]);
                a[mi][3] = __float_as_uint(ap[8*AST + 4]);
            }
            #pragma unroll
            for (int j = 0; j < 8; j++) {
                const float* bp = Bs + (nbase + j*8)*AST + k;
                uint32_t b0 = __float_as_uint(bp[0]);
                uint32_t b1 = __float_as_uint(bp[4]);
                mma_tf32(acc[0][j], a[0][0], a[0][1], a[0][2], a[0][3], b0, b1);
                mma_tf32(acc[1][j], a[1][0], a[1][1], a[1][2], a[1][3], b0, b1);
            }
        }
        __syncthreads();
    }

    // epilogue: z = acc + dvec + cov*wc; partial += vw * tanh(z); quad-reduce
    #pragma unroll
    for (int mi = 0; mi < 2; mi++) {
        const int r0 = wm*32 + mi*16 + gid;
        const int r1 = r0 + 8;
        const float cv0 = s_cov[r0], cv1 = s_cov[r1];
        float p0 = 0.f, p1 = 0.f;
        #pragma unroll
        for (int j = 0; j < 8; j++) {
            const int n0 = wn*64 + j*8 + qid*2;
            const float d0 = s_dvec[n0],   d1 = s_dvec[n0+1];
            const float w0 = s_wc[n0],     w1 = s_wc[n0+1];
            const float v0 = s_vw[n0],     v1 = s_vw[n0+1];
            float z, t;
            z = acc[mi][j][0] + d0 + cv0*w0;
            asm("tanh.approx.f32 %0, %1;" : "=f"(t) : "f"(z));  p0 = fmaf(v0, t, p0);
            z = acc[mi][j][1] + d1 + cv0*w1;
            asm("tanh.approx.f32 %0, %1;" : "=f"(t) : "f"(z));  p0 = fmaf(v1, t, p0);
            z = acc[mi][j][2] + d0 + cv1*w0;
            asm("tanh.approx.f32 %0, %1;" : "=f"(t) : "f"(z));  p1 = fmaf(v0, t, p1);
            z = acc[mi][j][3] + d1 + cv1*w1;
            asm("tanh.approx.f32 %0, %1;" : "=f"(t) : "f"(z));  p1 = fmaf(v1, t, p1);
        }
        p0 += __shfl_xor_sync(0xffffffffu, p0, 1);
        p0 += __shfl_xor_sync(0xffffffffu, p0, 2);
        p1 += __shfl_xor_sync(0xffffffffu, p1, 1);
        p1 += __shfl_xor_sync(0xffffffffu, p1, 2);
        if (qid == 0) {
            // two warps (wn=0,1) hold partials for the same rows -> separate slots
            float* dst = g_att_part + (nb*2 + wn)*NROWS*2;  // see note below
            // simpler: index by (nb, wn) as 8 slots of half-partials
            dst = g_att_part;  // overwritten below
            (void)dst;
            g_att_part[(size_t)(nb)*NROWS + row0 + r0] = 0.f; // placeholder (never used)
        }
        // proper write: combine wn halves via smem
        __shared__ float s_half[2][MT];
        if (qid == 0) { s_half[wn][r0] = p0; s_half[wn][r1] = p1; }
        __syncthreads();
        if (qid == 0 && wn == 0) {
            g_att_part[(size_t)nb*NROWS + row0 + r0] = p0 + s_half[1][r0];
            g_att_part[(size_t)nb*NROWS + row0 + r1] = p1 + s_half[1][r1];
        }
        __syncthreads();
    }
}

// ---------------------------------------------------------------------------
// softmax + coverage (sums the 4 N-block partials)
// ---------------------------------------------------------------------------
__global__ void softmax_kernel(const int* __restrict__ lens,
                               const float* __restrict__ cov,
                               float* __restrict__ out) {
    __shared__ float s[Ss];
    __shared__ float red[9];
    const int b = blockIdx.x;
    const int tid = threadIdx.x;
    const int len = lens[b];
    const float NEG_INF = __int_as_float(0xff800000);

    float mx = NEG_INF;
    for (int i = tid; i < Ss; i += 256) {
        float v = NEG_INF;
        if (i < len) {
            v = g_att_part[b*Ss + i]
              + g_att_part[NROWS + b*Ss + i]
              + g_att_part[2*NROWS + b*Ss + i]
              + g_att_part[3*NROWS + b*Ss + i];
        }
        s[i] = v;
        mx = fmaxf(mx, v);
    }
    #pragma unroll
    for (int m = 16; m >= 1; m >>= 1)
        mx = fmaxf(mx, __shfl_xor_sync(0xffffffffu, mx, m));
    if ((tid & 31) == 0) red[tid >> 5] = mx;
    __syncthreads();
    if (tid == 0) {
        float m = red[0];
        #pragma unroll
        for (int i = 1; i < 8; i++) m = fmaxf(m, red[i]);
        red[8] = m;
    }
    __syncthreads();
    mx = red[8];

    float sum = 0.f;
    for (int i = tid; i < Ss; i += 256) {
        float e = __expf(s[i] - mx);
        s[i] = e;
        sum += e;
    }
    #pragma unroll
    for (int m = 16; m >= 1; m >>= 1)
        sum += __shfl_xor_sync(0xffffffffu, sum, m);
    __syncthreads();
    if ((tid & 31) == 0) red[tid >> 5] = sum;
    __syncthreads();
    if (tid == 0) {
        float t = 0.f;
        #pragma unroll
        for (int i = 0; i < 8; i++) t += red[i];
        red[8] = t;
    }
    __syncthreads();
    const float inv = __fdividef(1.0f, red[8]);

    for (int i = tid; i < Ss; i += 256) {
        float w = s[i] * inv;
        out[b*Ss + i] = w;
        out[Bb*Ss + b*Ss + i] = cov[b*Ss + i] + w;
    }
}

// ---------------------------------------------------------------------------
extern "C" void kernel_launch(void* const* d_in, const int* in_sizes, int n_in,
                              void* d_out, int out_size) {
    const float* dec_input = (const float*)d_in[0];
    const float* enc       = (const float*)d_in[1];
    const int*   lens      = (const int*)  d_in[2];
    const float* cov       = (const float*)d_in[3];
    const float* W         = (const float*)d_in[4];
    const float* bias      = (const float*)d_in[5];
    const float* v_w       = (const float*)d_in[6];
    float* out = (float*)d_out;

    prep_kernel<<<289, 256>>>(dec_input, W, bias);

    static int configured = 0;
    if (!configured) {
        cudaFuncSetAttribute(gemm_kernel,
                             cudaFuncAttributeMaxDynamicSharedMemorySize, SMEM_DYN);
        configured = 1;
    }
    gemm_kernel<<<(NROWS/MT)*4, 256, SMEM_DYN>>>(enc, cov, v_w);

    softmax_kernel<<<Bb, 256>>>(lens, cov, out);
}

// round 4
// speedup vs baseline: 6.2612x; 1.5061x over previous
#include <cuda_runtime.h>
#include <cuda_fp16.h>
#include <cstdint>

#define Bb 32
#define Ss 2048
#define Hh 512
#define Ee 512
#define NROWS (Bb*Ss)

// ---- device scratch ----
__device__ __half g_Wh[Hh*Hh];      // W_enc^T [n][k] fp16   (GEMM B)
__device__ float  g_WsT[Ee*Hh];     // W_s^T  [h][e]
__device__ float  g_WcT[Hh*Hh];     // W_cov^T [h][k]
__device__ float  g_dvec[Bb*Hh];    // dec_proj + bias
__device__ float  g_wc_sum[Hh];
__device__ float  g_att[NROWS];

// ---- GEMM geometry ----
#define MT 128
#define AS_STRIDE 520                 // halves per A row (512 + 8 pad)
#define BS_STRIDE 72                  // halves per B row (64 + 8 pad)
#define AS_BYTES (128*AS_STRIDE*2)    // 133120
#define BS_BYTES (128*BS_STRIDE*2)    // 18432
#define OFF_BS   AS_BYTES
#define OFF_DVEC (AS_BYTES + 2*BS_BYTES)   // 169984
#define OFF_WC   (OFF_DVEC + 2048)
#define OFF_VW   (OFF_WC + 2048)
#define OFF_COV  (OFF_VW + 2048)
#define OFF_HALF (OFF_COV + 512)
#define SMEM_DYN (OFF_HALF + 1024)         // 177664

__device__ __forceinline__ uint32_t smem_u32(const void* p) {
    uint32_t a;
    asm("{ .reg .u64 t; cvta.to.shared.u64 t, %1; cvt.u32.u64 %0, t; }" : "=r"(a) : "l"(p));
    return a;
}
#define CP16(dst, src) asm volatile("cp.async.cg.shared.global [%0], [%1], 16;" :: "r"(dst), "l"(src))
#define CP_COMMIT()    asm volatile("cp.async.commit_group;" ::: "memory")
#define CP_WAIT1()     asm volatile("cp.async.wait_group 1;" ::: "memory")
#define CP_WAIT0()     asm volatile("cp.async.wait_group 0;" ::: "memory")

__device__ __forceinline__ void mma_f16(float* c, const uint32_t* a,
                                        uint32_t b0, uint32_t b1) {
    asm volatile(
        "mma.sync.aligned.m16n8k16.row.col.f32.f16.f16.f32 "
        "{%0,%1,%2,%3}, {%4,%5,%6,%7}, {%8,%9}, {%0,%1,%2,%3};"
        : "+f"(c[0]), "+f"(c[1]), "+f"(c[2]), "+f"(c[3])
        : "r"(a[0]), "r"(a[1]), "r"(a[2]), "r"(a[3]), "r"(b0), "r"(b1));
}

// ---------------------------------------------------------------------------
// P1: three 512x512 transposes. blk<256: W_enc -> g_Wh (fp16).
//     blk<512: W_s -> g_WsT.  blk<768: W_cov -> g_WcT.
// ---------------------------------------------------------------------------
__global__ void prep1_kernel(const float* __restrict__ W) {
    __shared__ float t[32][33];
    const int blk = blockIdx.x, tid = threadIdx.x;
    const int mat = blk >> 8;                 // 0,1,2
    const int loc = blk & 255;
    const int bc = loc & 15, br = loc >> 4;
    const int lx = tid & 31, ly = tid >> 5;
    const float* src = W + (size_t)mat*Hh*Hh;
    #pragma unroll
    for (int i = 0; i < 4; i++)
        t[ly + 8*i][lx] = src[(size_t)(br*32 + ly + 8*i)*Hh + bc*32 + lx];
    __syncthreads();
    if (mat == 0) {
        #pragma unroll
        for (int i = 0; i < 4; i++)
            g_Wh[(size_t)(bc*32 + ly + 8*i)*Hh + br*32 + lx] = __float2half_rn(t[lx][ly + 8*i]);
    } else if (mat == 1) {
        #pragma unroll
        for (int i = 0; i < 4; i++)
            g_WsT[(size_t)(bc*32 + ly + 8*i)*Hh + br*32 + lx] = t[lx][ly + 8*i];
    } else {
        #pragma unroll
        for (int i = 0; i < 4; i++)
            g_WcT[(size_t)(bc*32 + ly + 8*i)*Hh + br*32 + lx] = t[lx][ly + 8*i];
    }
}

// ---------------------------------------------------------------------------
// P2: warp-per-dot GEMV. blk<2048: dvec[b][h] = dec[b]·WsT[h] + bias[h]
//     blk>=2048 (64 blocks): wc_sum[h] = rowsum(WcT[h])
// ---------------------------------------------------------------------------
__global__ void prep2_kernel(const float* __restrict__ dec_input,
                             const float* __restrict__ bias) {
    const int blk = blockIdx.x;
    const int wid = threadIdx.x >> 5, lane = threadIdx.x & 31;
    if (blk < 2048) {
        const int w = blk*8 + wid;
        const int b = w >> 9, h = w & 511;
        const float* dp = dec_input + (size_t)b*Ee;
        const float* wp = g_WsT + (size_t)h*Ee;
        float acc = 0.f;
        #pragma unroll
        for (int i = 0; i < 16; i++)
            acc = fmaf(dp[lane + 32*i], wp[lane + 32*i], acc);
        #pragma unroll
        for (int m = 16; m >= 1; m >>= 1)
            acc += __shfl_xor_sync(0xffffffffu, acc, m);
        if (lane == 0) g_dvec[b*Hh + h] = acc + bias[h];
    } else {
        const int h = (blk - 2048)*8 + wid;
        const float* wp = g_WcT + (size_t)h*Hh;
        float acc = 0.f;
        #pragma unroll
        for (int i = 0; i < 16; i++)
            acc += wp[lane + 32*i];
        #pragma unroll
        for (int m = 16; m >= 1; m >>= 1)
            acc += __shfl_xor_sync(0xffffffffu, acc, m);
        if (lane == 0) g_wc_sum[h] = acc;
    }
}

// ---------------------------------------------------------------------------
// GEMM: 512 CTAs, each M=128 rows x full N=512 (4 chunks of 128), fp16 mma.
// 256 threads: warp grid 4(M) x 2(N-half).
// ---------------------------------------------------------------------------
__global__ __launch_bounds__(256, 1) void gemm_kernel(
    const float* __restrict__ enc,
    const float* __restrict__ cov,
    const float* __restrict__ v_w)
{
    extern __shared__ char sm[];
    __half* As    = (__half*)sm;
    float* s_dvec = (float*)(sm + OFF_DVEC);
    float* s_wc   = (float*)(sm + OFF_WC);
    float* s_vw   = (float*)(sm + OFF_VW);
    float* s_cov  = (float*)(sm + OFF_COV);
    float* s_half = (float*)(sm + OFF_HALF);   // [2][128]

    const uint32_t sb = smem_u32(sm);
    const int tid = threadIdx.x;
    const int wid = tid >> 5, lane = tid & 31;
    const int gid = lane >> 2, qid = lane & 3;
    const int wm = wid >> 1, wn = wid & 1;
    const int row0 = blockIdx.x * MT;
    const int b = row0 >> 11;

    // B-chunk loader: q in [0,32): nc = q>>3 (N-chunk of 128), kc = q&7 (K-chunk of 64)
    const int ldr_n  = tid >> 1;           // 0..127
    const int ldr_k0 = (tid & 1) * 32;     // halves
    auto issueB = [&](int q) {
        const int nc = q >> 3, kc = q & 7;
        const uint32_t dst = sb + OFF_BS + (q & 1)*BS_BYTES + ldr_n*(BS_STRIDE*2) + ldr_k0*2;
        const __half* src = g_Wh + (size_t)(nc*128 + ldr_n)*Hh + kc*64 + ldr_k0;
        #pragma unroll
        for (int j = 0; j < 4; j++)
            CP16(dst + j*16, src + j*8);
    };

    issueB(0);
    CP_COMMIT();

    // epilogue constants
    for (int i = tid; i < Hh; i += 256) {
        s_dvec[i] = g_dvec[b*Hh + i];
        s_wc[i]   = g_wc_sum[i];
        s_vw[i]   = v_w[i];
    }
    if (tid < MT) s_cov[tid] = cov[row0 + tid];

    // A tile: 128 x 512 fp32 -> fp16 smem
    {
        const float4* encv = (const float4*)(enc + (size_t)row0 * Hh);
        #pragma unroll 8
        for (int i = 0; i < 64; i++) {
            int idx = tid + i*256;
            int r = idx >> 7, c4 = idx & 127;
            float4 v = encv[r*128 + c4];
            __half2 h0 = __float22half2_rn(make_float2(v.x, v.y));
            __half2 h1 = __float22half2_rn(make_float2(v.z, v.w));
            char* dst = sm + r*(AS_STRIDE*2) + c4*8;
            *(__half2*)dst = h0;
            *(__half2*)(dst + 4) = h1;
        }
    }
    __syncthreads();

    float p[2][2] = {{0.f, 0.f}, {0.f, 0.f}};
    float acc[2][8][4];
    const int ra = wm*32 + gid;

    #pragma unroll 1
    for (int q = 0; q < 32; q++) {
        const int nc = q >> 3, kc = q & 7;
        if (kc == 0) {
            #pragma unroll
            for (int mi = 0; mi < 2; mi++)
                #pragma unroll
                for (int j = 0; j < 8; j++)
                    #pragma unroll
                    for (int c = 0; c < 4; c++) acc[mi][j][c] = 0.f;
        }
        if (q < 31) { issueB(q + 1); CP_COMMIT(); CP_WAIT1(); }
        else        { CP_WAIT0(); }
        __syncthreads();

        const __half* Bs = (const __half*)(sm + OFF_BS + (q & 1)*BS_BYTES);

        #pragma unroll
        for (int ks = 0; ks < 4; ks++) {
            const int ka = kc*64 + ks*16 + qid*2;     // A k (global)
            uint32_t a[2][4];
            #pragma unroll
            for (int mi = 0; mi < 2; mi++) {
                const __half* ap = As + (size_t)(ra + mi*16)*AS_STRIDE + ka;
                a[mi][0] = *(const uint32_t*)ap;
                a[mi][1] = *(const uint32_t*)(ap + 8*AS_STRIDE);
                a[mi][2] = *(const uint32_t*)(ap + 8);
                a[mi][3] = *(const uint32_t*)(ap + 8*AS_STRIDE + 8);
            }
            const int kb = ks*16 + qid*2;             // B k (chunk-local)
            #pragma unroll
            for (int j = 0; j < 8; j++) {
                const __half* bp = Bs + (size_t)(wn*64 + j*8 + gid)*BS_STRIDE + kb;
                uint32_t b0 = *(const uint32_t*)bp;
                uint32_t b1 = *(const uint32_t*)(bp + 8);
                mma_f16(acc[0][j], a[0], b0, b1);
                mma_f16(acc[1][j], a[1], b0, b1);
            }
        }
        __syncthreads();

        if (kc == 7) {
            // fused epilogue for N-chunk nc
            #pragma unroll
            for (int mi = 0; mi < 2; mi++) {
                const int r0 = wm*32 + mi*16 + gid;
                const float cv0 = s_cov[r0], cv1 = s_cov[r0 + 8];
                #pragma unroll
                for (int j = 0; j < 8; j++) {
                    const int n0 = nc*128 + wn*64 + j*8 + qid*2;
                    const float d0 = s_dvec[n0], d1 = s_dvec[n0+1];
                    const float w0 = s_wc[n0],   w1 = s_wc[n0+1];
                    const float v0 = s_vw[n0],   v1 = s_vw[n0+1];
                    float z, t;
                    z = acc[mi][j][0] + d0 + cv0*w0;
                    asm("tanh.approx.f32 %0, %1;" : "=f"(t) : "f"(z));  p[mi][0] = fmaf(v0, t, p[mi][0]);
                    z = acc[mi][j][1] + d1 + cv0*w1;
                    asm("tanh.approx.f32 %0, %1;" : "=f"(t) : "f"(z));  p[mi][0] = fmaf(v1, t, p[mi][0]);
                    z = acc[mi][j][2] + d0 + cv1*w0;
                    asm("tanh.approx.f32 %0, %1;" : "=f"(t) : "f"(z));  p[mi][1] = fmaf(v0, t, p[mi][1]);
                    z = acc[mi][j][3] + d1 + cv1*w1;
                    asm("tanh.approx.f32 %0, %1;" : "=f"(t) : "f"(z));  p[mi][1] = fmaf(v1, t, p[mi][1]);
                }
            }
        }
    }

    // reduce over qid lanes, combine the two wn half-partials, store
    #pragma unroll
    for (int mi = 0; mi < 2; mi++)
        #pragma unroll
        for (int h = 0; h < 2; h++) {
            float x = p[mi][h];
            x += __shfl_xor_sync(0xffffffffu, x, 1);
            x += __shfl_xor_sync(0xffffffffu, x, 2);
            p[mi][h] = x;
        }
    if (qid == 0) {
        #pragma unroll
        for (int mi = 0; mi < 2; mi++)
            #pragma unroll
            for (int h = 0; h < 2; h++)
                s_half[wn*128 + wm*32 + mi*16 + gid + h*8] = p[mi][h];
    }
    __syncthreads();
    if (qid == 0 && wn == 0) {
        #pragma unroll
        for (int mi = 0; mi < 2; mi++)
            #pragma unroll
            for (int h = 0; h < 2; h++) {
                const int r = wm*32 + mi*16 + gid + h*8;
                g_att[row0 + r] = p[mi][h] + s_half[128 + r];
            }
    }
}

// ---------------------------------------------------------------------------
// softmax + coverage
// ---------------------------------------------------------------------------
__global__ void softmax_kernel(const int* __restrict__ lens,
                               const float* __restrict__ cov,
                               float* __restrict__ out) {
    __shared__ float s[Ss];
    __shared__ float red[9];
    const int b = blockIdx.x;
    const int tid = threadIdx.x;
    const int len = lens[b];
    const float NEG_INF = __int_as_float(0xff800000);

    float mx = NEG_INF;
    for (int i = tid; i < Ss; i += 256) {
        float v = (i < len) ? g_att[b*Ss + i] : NEG_INF;
        s[i] = v;
        mx = fmaxf(mx, v);
    }
    #pragma unroll
    for (int m = 16; m >= 1; m >>= 1)
        mx = fmaxf(mx, __shfl_xor_sync(0xffffffffu, mx, m));
    if ((tid & 31) == 0) red[tid >> 5] = mx;
    __syncthreads();
    if (tid == 0) {
        float m = red[0];
        #pragma unroll
        for (int i = 1; i < 8; i++) m = fmaxf(m, red[i]);
        red[8] = m;
    }
    __syncthreads();
    mx = red[8];

    float sum = 0.f;
    for (int i = tid; i < Ss; i += 256) {
        float e = __expf(s[i] - mx);
        s[i] = e;
        sum += e;
    }
    #pragma unroll
    for (int m = 16; m >= 1; m >>= 1)
        sum += __shfl_xor_sync(0xffffffffu, sum, m);
    __syncthreads();
    if ((tid & 31) == 0) red[tid >> 5] = sum;
    __syncthreads();
    if (tid == 0) {
        float t = 0.f;
        #pragma unroll
        for (int i = 0; i < 8; i++) t += red[i];
        red[8] = t;
    }
    __syncthreads();
    const float inv = __fdividef(1.0f, red[8]);

    for (int i = tid; i < Ss; i += 256) {
        float w = s[i] * inv;
        out[b*Ss + i] = w;
        out[Bb*Ss + b*Ss + i] = cov[b*Ss + i] + w;
    }
}

// ---------------------------------------------------------------------------
extern "C" void kernel_launch(void* const* d_in, const int* in_sizes, int n_in,
                              void* d_out, int out_size) {
    const float* dec_input = (const float*)d_in[0];
    const float* enc       = (const float*)d_in[1];
    const int*   lens      = (const int*)  d_in[2];
    const float* cov       = (const float*)d_in[3];
    const float* W         = (const float*)d_in[4];
    const float* bias      = (const float*)d_in[5];
    const float* v_w       = (const float*)d_in[6];
    float* out = (float*)d_out;

    prep1_kernel<<<768, 256>>>(W);
    prep2_kernel<<<2048 + 64, 256>>>(dec_input, bias);

    static int configured = 0;
    if (!configured) {
        cudaFuncSetAttribute(gemm_kernel,
                             cudaFuncAttributeMaxDynamicSharedMemorySize, SMEM_DYN);
        configured = 1;
    }
    gemm_kernel<<<NROWS/MT, 256, SMEM_DYN>>>(enc, cov, v_w);

    softmax_kernel<<<Bb, 256>>>(lens, cov, out);
}